// round 4
// baseline (speedup 1.0000x reference)
#include <cuda_runtime.h>
#include <cuda_bf16.h>
#include <cstdint>
#include <math.h>

#define NN   50000
#define NE   320000
#define NR   3
#define IND  768
#define HIDD 256
#define OUTD 64

typedef __nv_bfloat16 bf16;

// ---------------- scratch ----------------------------------------------------------
__device__ bf16  g_ahi[(size_t)NN * IND];
__device__ bf16  g_alo[(size_t)NN * IND];
__device__ bf16  g_wthi[HIDD * IND];            // transposed weight hi [N,K]
__device__ bf16  g_wtlo[HIDD * IND];
__device__ bf16  g_hhi[NN * HIDD];              // conv2 output split (head GEMM A)
__device__ bf16  g_hlo[NN * HIDD];
__device__ float g_h0[NN * HIDD];
__device__ float g_h2[NN * HIDD];
__device__ float g_h3[NN * OUTD];
__device__ float g_qi[NN * NR];
__device__ float g_kj[NN * NR];
__device__ float g_aperm[NE];
__device__ int   g_cnt[NN];
__device__ int   g_off[NN + 1];
__device__ int   g_pack[NE];
__device__ int   g_epos[NE];
__device__ float g_wq[NR * HIDD];
__device__ float g_wk[NR * HIDD];

// ---------------- helpers ----------------------------------------------------------
__device__ __forceinline__ uint32_t smem_u32(const void* p) {
    uint32_t a;
    asm("{ .reg .u64 t; cvta.to.shared.u64 t, %1; cvt.u32.u64 %0, t; }" : "=r"(a) : "l"(p));
    return a;
}
#define SW128(o) ((o) ^ (((o) >> 3) & 0x70))

#define LDSM4(r0, r1, r2, r3, addr) \
    asm volatile("ldmatrix.sync.aligned.m8n8.x4.shared.b16 {%0,%1,%2,%3}, [%4];" \
        : "=r"(r0), "=r"(r1), "=r"(r2), "=r"(r3) : "r"(addr))

#define MMA16816(cf, af, b0, b1) \
    asm volatile("mma.sync.aligned.m16n8k16.row.col.f32.bf16.bf16.f32 " \
        "{%0,%1,%2,%3}, {%4,%5,%6,%7}, {%8,%9}, {%0,%1,%2,%3};" \
        : "+f"((cf)[0]), "+f"((cf)[1]), "+f"((cf)[2]), "+f"((cf)[3]) \
        : "r"((af)[0]), "r"((af)[1]), "r"((af)[2]), "r"((af)[3]), "r"(b0), "r"(b1))

// ---------------- GEMM via mma.sync bf16 hi/lo split --------------------------------
// C[M,N] = A[M,K] @ B^T (B stored [N,K] K-major).  A,B given as hi/lo bf16 pairs.
// CTA tile: 128 x NBLK.  mode: 0=f32 out, 1=f32+relu, 2=bf16 hi/lo out.
template<int NBLK>
__global__ void __launch_bounds__(256, 2)
gemm_mma(const bf16* __restrict__ Ahi, const bf16* __restrict__ Alo,
         const bf16* __restrict__ Bhi, const bf16* __restrict__ Blo,
         const float* __restrict__ bias, float* __restrict__ C,
         bf16* __restrict__ Chi, bf16* __restrict__ Clo,
         int M, int K, int N, int mode)
{
    constexpr int WN = NBLK / 32;       // warps along N
    constexpr int WM = 8 / WN;          // warps along M
    constexpr int MT = 128 / WM / 16;   // m16 tiles per warp

    extern __shared__ char smem[];
    const uint32_t sA_hi = smem_u32(smem);
    const uint32_t sA_lo = sA_hi + 16384;
    const uint32_t sB_hi = sA_hi + 32768;
    const uint32_t sB_lo = sB_hi + NBLK * 128;

    const int tid = threadIdx.x, wid = tid >> 5, lane = tid & 31;
    const int bm = blockIdx.x * 128;
    const int bn = blockIdx.y * NBLK;
    const int warp_m = wid / WN, warp_n = wid % WN;
    const int m0 = warp_m * (MT * 16);
    const int n0 = warp_n * 32;

    float c[MT][4][4];
#pragma unroll
    for (int i = 0; i < MT; i++)
#pragma unroll
        for (int j = 0; j < 4; j++)
#pragma unroll
            for (int l = 0; l < 4; l++) c[i][j][l] = 0.f;

    // precomputed ldmatrix offsets (within-tile, swizzled per ks inside loop)
    const int a_row = (lane & 15);
    const uint32_t a_sel = (uint32_t)((lane >> 4) << 4);
    const int b_row = (lane & 7) + ((lane >> 4) << 3);
    const uint32_t b_sel = (uint32_t)((lane & 8) << 1);

    const int NCH = K >> 6;
    for (int ch = 0; ch < NCH; ch++) {
        const size_t kofs = (size_t)ch * 64;
        for (int i = tid; i < 1024; i += 256) {            // A: 128 rows x 8 chunks
            int row = i >> 3, ck = i & 7;
            int gr = bm + row; if (gr > M - 1) gr = M - 1;
            uint32_t off = SW128((uint32_t)(row * 128 + ck * 16));
            *(uint4*)(smem + off) =
                *(const uint4*)((const char*)(Ahi + (size_t)gr * K + kofs) + ck * 16);
            *(uint4*)(smem + 16384 + off) =
                *(const uint4*)((const char*)(Alo + (size_t)gr * K + kofs) + ck * 16);
        }
        for (int i = tid; i < NBLK * 8; i += 256) {        // B: NBLK rows x 8 chunks
            int row = i >> 3, ck = i & 7;
            uint32_t off = SW128((uint32_t)(row * 128 + ck * 16));
            *(uint4*)(smem + 32768 + off) =
                *(const uint4*)((const char*)(Bhi + (size_t)(bn + row) * K + kofs) + ck * 16);
            *(uint4*)(smem + 32768 + NBLK * 128 + off) =
                *(const uint4*)((const char*)(Blo + (size_t)(bn + row) * K + kofs) + ck * 16);
        }
        __syncthreads();

#pragma unroll
        for (int ks = 0; ks < 4; ks++) {
            uint32_t bh[4][2], bl[4][2];
#pragma unroll
            for (int np = 0; np < 4; np += 2) {
                int row = n0 + np * 8 + b_row;
                uint32_t off = SW128((uint32_t)(row * 128 + ks * 32) + b_sel);
                LDSM4(bh[np][0], bh[np][1], bh[np + 1][0], bh[np + 1][1], sB_hi + off);
                LDSM4(bl[np][0], bl[np][1], bl[np + 1][0], bl[np + 1][1], sB_lo + off);
            }
            uint32_t a[MT][4];
            uint32_t aoff[MT];
#pragma unroll
            for (int mt = 0; mt < MT; mt++) {
                int row = m0 + mt * 16 + a_row;
                aoff[mt] = SW128((uint32_t)(row * 128 + ks * 32) + a_sel);
                LDSM4(a[mt][0], a[mt][1], a[mt][2], a[mt][3], sA_hi + aoff[mt]);
            }
            // pass 1+2: Ahi*Bhi, Ahi*Blo
#pragma unroll
            for (int mt = 0; mt < MT; mt++)
#pragma unroll
                for (int nt = 0; nt < 4; nt++) {
                    MMA16816(c[mt][nt], a[mt], bh[nt][0], bh[nt][1]);
                    MMA16816(c[mt][nt], a[mt], bl[nt][0], bl[nt][1]);
                }
            // pass 3: Alo*Bhi
#pragma unroll
            for (int mt = 0; mt < MT; mt++)
                LDSM4(a[mt][0], a[mt][1], a[mt][2], a[mt][3], sA_lo + aoff[mt]);
#pragma unroll
            for (int mt = 0; mt < MT; mt++)
#pragma unroll
                for (int nt = 0; nt < 4; nt++)
                    MMA16816(c[mt][nt], a[mt], bh[nt][0], bh[nt][1]);
        }
        __syncthreads();
    }

    // epilogue: c-frag thread mapping: rows lane/4 (+8), cols (lane%4)*2 (+1)
#pragma unroll
    for (int mt = 0; mt < MT; mt++) {
#pragma unroll
        for (int nt = 0; nt < 4; nt++) {
            int col = bn + n0 + nt * 8 + (lane & 3) * 2;
            float b0 = bias[col], b1 = bias[col + 1];
#pragma unroll
            for (int h = 0; h < 2; h++) {
                int r = bm + m0 + mt * 16 + (lane >> 2) + h * 8;
                if (r >= M) continue;
                float v0 = c[mt][nt][h * 2 + 0] + b0;
                float v1 = c[mt][nt][h * 2 + 1] + b1;
                if (mode == 1) { v0 = fmaxf(v0, 0.f); v1 = fmaxf(v1, 0.f); }
                if (mode == 2) {
                    bf16 h0 = __float2bfloat16(v0);
                    bf16 h1 = __float2bfloat16(v1);
                    bf16 l0 = __float2bfloat16(v0 - __bfloat162float(h0));
                    bf16 l1 = __float2bfloat16(v1 - __bfloat162float(h1));
                    ushort2 ph = make_ushort2(__bfloat16_as_ushort(h0), __bfloat16_as_ushort(h1));
                    ushort2 pl = make_ushort2(__bfloat16_as_ushort(l0), __bfloat16_as_ushort(l1));
                    *(ushort2*)(Chi + (size_t)r * N + col) = ph;
                    *(ushort2*)(Clo + (size_t)r * N + col) = pl;
                } else {
                    *(float2*)(C + (size_t)r * N + col) = make_float2(v0, v1);
                }
            }
        }
    }
}

// ---------------- conversions ------------------------------------------------------
__global__ void split_f32(const float* __restrict__ src, bf16* __restrict__ hi,
                          bf16* __restrict__ lo, size_t n)
{
    size_t i = ((size_t)blockIdx.x * blockDim.x + threadIdx.x) * 8;
    if (i >= n) return;
    float4 a = *(const float4*)(src + i);
    float4 b = *(const float4*)(src + i + 4);
    float v[8] = {a.x, a.y, a.z, a.w, b.x, b.y, b.z, b.w};
    uint4 sh, sl;
    unsigned short* ph = (unsigned short*)&sh;
    unsigned short* pl = (unsigned short*)&sl;
#pragma unroll
    for (int j = 0; j < 8; j++) {
        bf16 h = __float2bfloat16(v[j]);
        bf16 l = __float2bfloat16(v[j] - __bfloat162float(h));
        ph[j] = __bfloat16_as_ushort(h);
        pl[j] = __bfloat16_as_ushort(l);
    }
    *(uint4*)(hi + i) = sh;
    *(uint4*)(lo + i) = sl;
}

// W[K,N] fp32 -> T_hi/T_lo[N,K] bf16 (transpose + split)
__global__ void wsplit_t(const float* __restrict__ W, bf16* __restrict__ Thi,
                         bf16* __restrict__ Tlo, int K, int N)
{
    __shared__ float t[32][33];
    int n0 = blockIdx.x * 32, k0 = blockIdx.y * 32;
    t[threadIdx.y][threadIdx.x] = W[(size_t)(k0 + threadIdx.y) * N + n0 + threadIdx.x];
    __syncthreads();
    float v = t[threadIdx.x][threadIdx.y];
    bf16 h = __float2bfloat16(v);
    bf16 l = __float2bfloat16(v - __bfloat162float(h));
    size_t o = (size_t)(n0 + threadIdx.y) * K + k0 + threadIdx.x;
    Thi[o] = h; Tlo[o] = l;
}

// ---------------- CSR construction -------------------------------------------------
__global__ void hist_kernel(const int* __restrict__ ei, int* __restrict__ cnt)
{
    int e = blockIdx.x * blockDim.x + threadIdx.x;
    if (e < NE) atomicAdd(&cnt[ei[NE + e]], 1);
}

__global__ void scan_kernel(const int* __restrict__ cnt, int* __restrict__ off)
{
    __shared__ int sums[1024];
    const int t = threadIdx.x;
    const int CH = (NN + 1023) / 1024;
    const int base = t * CH;
    int mysum = 0;
    for (int i = 0; i < CH; i++) {
        int idx = base + i;
        if (idx < NN) mysum += cnt[idx];
    }
    sums[t] = mysum;
    __syncthreads();
    for (int d = 1; d < 1024; d <<= 1) {
        int v = 0;
        if (t >= d) v = sums[t - d];
        __syncthreads();
        sums[t] += v;
        __syncthreads();
    }
    int run = sums[t] - mysum;
    for (int i = 0; i < CH; i++) {
        int idx = base + i;
        if (idx < NN) { off[idx] = run; run += cnt[idx]; }
    }
    if (t == 1023) off[NN] = sums[1023];
}

__global__ void fill_kernel(const int* __restrict__ ei, const int* __restrict__ etp,
                            const int* __restrict__ off, int* __restrict__ cur,
                            int* __restrict__ pack, int* __restrict__ epos)
{
    int e = blockIdx.x * blockDim.x + threadIdx.x;
    if (e >= NE) return;
    int d = ei[NE + e];
    int p = off[d] + atomicAdd(&cur[d], 1);
    pack[p] = ei[e] | (etp[e] << 20);
    epos[e] = p;
}

// ---------------- attention scalar path --------------------------------------------
__global__ void wqwk_kernel(const float* __restrict__ W, const float* __restrict__ q,
                            const float* __restrict__ k,
                            float* __restrict__ wq, float* __restrict__ wk)
{
    __shared__ float qs[HIDD], ks[HIDD];
    int r = blockIdx.x, c = threadIdx.x;
    qs[c] = q[c]; ks[c] = k[c];
    __syncthreads();
    const float* Wrc = W + ((size_t)r * HIDD + c) * HIDD;
    float aq = 0.f, ak = 0.f;
    for (int o = 0; o < HIDD; o++) {
        float w = Wrc[o];
        aq = fmaf(w, qs[o], aq);
        ak = fmaf(w, ks[o], ak);
    }
    wq[r * HIDD + c] = aq;
    wk[r * HIDD + c] = ak;
}

__global__ void qikj_kernel(const float* __restrict__ h, const float* __restrict__ wq,
                            const float* __restrict__ wk,
                            float* __restrict__ qi, float* __restrict__ kj)
{
    int warp = (blockIdx.x * blockDim.x + threadIdx.x) >> 5;
    int lane = threadIdx.x & 31;
    if (warp >= NN) return;
    const float4* hp = (const float4*)(h + (size_t)warp * HIDD + lane * 8);
    float4 h0 = hp[0], h1 = hp[1];
    float dq[NR], dk[NR];
#pragma unroll
    for (int r = 0; r < NR; r++) {
        const float4* qp = (const float4*)(wq + r * HIDD + lane * 8);
        const float4* kp = (const float4*)(wk + r * HIDD + lane * 8);
        float4 q0 = qp[0], q1 = qp[1];
        float4 k0 = kp[0], k1 = kp[1];
        dq[r] = h0.x*q0.x + h0.y*q0.y + h0.z*q0.z + h0.w*q0.w
              + h1.x*q1.x + h1.y*q1.y + h1.z*q1.z + h1.w*q1.w;
        dk[r] = h0.x*k0.x + h0.y*k0.y + h0.z*k0.z + h0.w*k0.w
              + h1.x*k1.x + h1.y*k1.y + h1.z*k1.z + h1.w*k1.w;
    }
#pragma unroll
    for (int d = 16; d; d >>= 1) {
#pragma unroll
        for (int r = 0; r < NR; r++) {
            dq[r] += __shfl_xor_sync(0xffffffffu, dq[r], d);
            dk[r] += __shfl_xor_sync(0xffffffffu, dk[r], d);
        }
    }
    if (lane == 0) {
#pragma unroll
        for (int r = 0; r < NR; r++) {
            qi[warp * NR + r] = dq[r];
            kj[warp * NR + r] = dk[r];
        }
    }
}

__global__ void alpha_kernel(const int* __restrict__ ei, const int* __restrict__ etp,
                             const float* __restrict__ qi, const float* __restrict__ kj,
                             const int* __restrict__ epos, float* __restrict__ aperm)
{
    int e = blockIdx.x * blockDim.x + threadIdx.x;
    if (e >= NE) return;
    int s = ei[e], d = ei[NE + e], t = etp[e];
    float a = qi[d * NR + t] + kj[s * NR + t];
    a = (a > 0.f) ? a : 0.2f * a;
    aperm[epos[e]] = a;
}

// ---------------- softmax + aggregation; emits bf16 hi/lo directly ------------------
__device__ __forceinline__ void store_split8(bf16* hi, bf16* lo, const float* v)
{
    uint4 sh, sl;
    unsigned short* ph = (unsigned short*)&sh;
    unsigned short* pl = (unsigned short*)&sl;
#pragma unroll
    for (int j = 0; j < 8; j++) {
        bf16 h = __float2bfloat16(v[j]);
        bf16 l = __float2bfloat16(v[j] - __bfloat162float(h));
        ph[j] = __bfloat16_as_ushort(h);
        pl[j] = __bfloat16_as_ushort(l);
    }
    *(uint4*)hi = sh;
    *(uint4*)lo = sl;
}

__global__ void aggregate_kernel(const float* __restrict__ h, const float* __restrict__ aperm,
                                 const int* __restrict__ pack, const int* __restrict__ off,
                                 bf16* __restrict__ shi, bf16* __restrict__ slo)
{
    int node = (blockIdx.x * blockDim.x + threadIdx.x) >> 5;
    int lane = threadIdx.x & 31;
    if (node >= NN) return;
    int o0 = off[node], o1 = off[node + 1];

    float a0[8], a1[8], a2[8];
#pragma unroll
    for (int j = 0; j < 8; j++) { a0[j] = 0.f; a1[j] = 0.f; a2[j] = 0.f; }

    if (o1 > o0) {
        float m = -3.4e38f;
        for (int p = o0 + lane; p < o1; p += 32) m = fmaxf(m, aperm[p]);
#pragma unroll
        for (int d = 16; d; d >>= 1) m = fmaxf(m, __shfl_xor_sync(0xffffffffu, m, d));
        float ssum = 0.f;
        for (int p = o0 + lane; p < o1; p += 32) ssum += __expf(aperm[p] - m);
#pragma unroll
        for (int d = 16; d; d >>= 1) ssum += __shfl_xor_sync(0xffffffffu, ssum, d);
        float inv = 1.f / (ssum + 1e-16f);

        for (int p = o0; p < o1; p++) {
            float w = __expf(aperm[p] - m) * inv;
            int pk = pack[p];
            int srcn = pk & 0xFFFFF;
            int t = pk >> 20;
            const float4* hp = (const float4*)(h + (size_t)srcn * HIDD + lane * 8);
            float4 v0 = hp[0], v1 = hp[1];
            float* a = (t == 0) ? a0 : (t == 1) ? a1 : a2;
            a[0] = fmaf(w, v0.x, a[0]); a[1] = fmaf(w, v0.y, a[1]);
            a[2] = fmaf(w, v0.z, a[2]); a[3] = fmaf(w, v0.w, a[3]);
            a[4] = fmaf(w, v1.x, a[4]); a[5] = fmaf(w, v1.y, a[5]);
            a[6] = fmaf(w, v1.z, a[6]); a[7] = fmaf(w, v1.w, a[7]);
        }
    }
    size_t base = (size_t)node * (NR * HIDD) + lane * 8;
    store_split8(shi + base,       slo + base,       a0);
    store_split8(shi + base + 256, slo + base + 256, a1);
    store_split8(shi + base + 512, slo + base + 512, a2);
}

// ---------------- classifier -------------------------------------------------------
__global__ void cls_kernel(const float* __restrict__ h3, const float* __restrict__ w_cls,
                           const float* __restrict__ b_cls, float* __restrict__ out)
{
    int node = (blockIdx.x * blockDim.x + threadIdx.x) >> 5;
    int lane = threadIdx.x & 31;
    if (node >= NN) return;
    float2 v = *(const float2*)(h3 + (size_t)node * OUTD + lane * 2);
    float4 w = *(const float4*)(w_cls + lane * 4);
    float s0 = v.x * w.x + v.y * w.z;
    float s1 = v.x * w.y + v.y * w.w;
#pragma unroll
    for (int d = 16; d; d >>= 1) {
        s0 += __shfl_xor_sync(0xffffffffu, s0, d);
        s1 += __shfl_xor_sync(0xffffffffu, s1, d);
    }
    if (lane == 0) {
        out[node * 2 + 0] = s0 + b_cls[0];
        out[node * 2 + 1] = s1 + b_cls[1];
    }
}

// ---------------- launcher ---------------------------------------------------------
extern "C" void kernel_launch(void* const* d_in, const int* in_sizes, int n_in,
                              void* d_out, int out_size)
{
    const float* x     = (const float*)d_in[0];
    const int*   ei    = (const int*)d_in[1];
    const int*   etp   = (const int*)d_in[2];
    const float* w_in  = (const float*)d_in[3];
    const float* b_in  = (const float*)d_in[4];
    const float* c1w   = (const float*)d_in[5];
    const float* c1q   = (const float*)d_in[6];
    const float* c1k   = (const float*)d_in[7];
    const float* c1b   = (const float*)d_in[8];
    const float* c2w   = (const float*)d_in[9];
    const float* c2q   = (const float*)d_in[10];
    const float* c2k   = (const float*)d_in[11];
    const float* c2b   = (const float*)d_in[12];
    const float* w_out = (const float*)d_in[13];
    const float* b_out = (const float*)d_in[14];
    const float* w_cls = (const float*)d_in[15];
    const float* b_cls = (const float*)d_in[16];
    float* out = (float*)d_out;

    bf16 *ahi, *alo, *wthi, *wtlo, *hhi, *hlo;
    float *h0, *h2, *h3, *qi, *kj, *aperm, *wq, *wk;
    int *cnt, *off, *pack, *epos;
    cudaGetSymbolAddress((void**)&ahi, g_ahi);
    cudaGetSymbolAddress((void**)&alo, g_alo);
    cudaGetSymbolAddress((void**)&wthi, g_wthi);
    cudaGetSymbolAddress((void**)&wtlo, g_wtlo);
    cudaGetSymbolAddress((void**)&hhi, g_hhi);
    cudaGetSymbolAddress((void**)&hlo, g_hlo);
    cudaGetSymbolAddress((void**)&h0, g_h0);
    cudaGetSymbolAddress((void**)&h2, g_h2);
    cudaGetSymbolAddress((void**)&h3, g_h3);
    cudaGetSymbolAddress((void**)&qi, g_qi);
    cudaGetSymbolAddress((void**)&kj, g_kj);
    cudaGetSymbolAddress((void**)&aperm, g_aperm);
    cudaGetSymbolAddress((void**)&wq, g_wq);
    cudaGetSymbolAddress((void**)&wk, g_wk);
    cudaGetSymbolAddress((void**)&cnt, g_cnt);
    cudaGetSymbolAddress((void**)&off, g_off);
    cudaGetSymbolAddress((void**)&pack, g_pack);
    cudaGetSymbolAddress((void**)&epos, g_epos);

    const int SMEM128 = 32768 + 2 * 128 * 128;   // 65536
    const int SMEM64  = 32768 + 2 * 64 * 128;    // 49152
    cudaFuncSetAttribute(gemm_mma<128>, cudaFuncAttributeMaxDynamicSharedMemorySize, SMEM128);
    cudaFuncSetAttribute(gemm_mma<64>,  cudaFuncAttributeMaxDynamicSharedMemorySize, SMEM64);

    const int EBLK = (NE + 255) / 256;
    const int WBLK = (NN * 32 + 255) / 256;
    const int GMM = (NN + 127) / 128;

    // input layer: h0 = relu(x @ w_in + b_in)
    split_f32<<<(int)(((size_t)NN * IND / 8 + 255) / 256), 256>>>(x, ahi, alo, (size_t)NN * IND);
    wsplit_t<<<dim3(HIDD / 32, IND / 32), dim3(32, 32)>>>(w_in, wthi, wtlo, IND, HIDD);
    gemm_mma<128><<<dim3(GMM, 2), 256, SMEM128>>>(ahi, alo, wthi, wtlo, b_in, h0,
                                                  nullptr, nullptr, NN, IND, HIDD, 1);

    // CSR by dst
    cudaMemsetAsync(cnt, 0, NN * sizeof(int));
    hist_kernel<<<EBLK, 256>>>(ei, cnt);
    scan_kernel<<<1, 1024>>>(cnt, off);
    cudaMemsetAsync(cnt, 0, NN * sizeof(int));
    fill_kernel<<<EBLK, 256>>>(ei, etp, off, cnt, pack, epos);

    // conv1: h2 = RGAT(h0)
    wqwk_kernel<<<NR, HIDD>>>(c1w, c1q, c1k, wq, wk);
    qikj_kernel<<<WBLK, 256>>>(h0, wq, wk, qi, kj);
    alpha_kernel<<<EBLK, 256>>>(ei, etp, qi, kj, epos, aperm);
    aggregate_kernel<<<WBLK, 256>>>(h0, aperm, pack, off, ahi, alo);
    wsplit_t<<<dim3(HIDD / 32, (NR * HIDD) / 32), dim3(32, 32)>>>(c1w, wthi, wtlo, NR * HIDD, HIDD);
    gemm_mma<128><<<dim3(GMM, 2), 256, SMEM128>>>(ahi, alo, wthi, wtlo, c1b, h2,
                                                  nullptr, nullptr, NN, NR * HIDD, HIDD, 0);

    // conv2: (hhi,hlo) = RGAT(h2) split
    wqwk_kernel<<<NR, HIDD>>>(c2w, c2q, c2k, wq, wk);
    qikj_kernel<<<WBLK, 256>>>(h2, wq, wk, qi, kj);
    alpha_kernel<<<EBLK, 256>>>(ei, etp, qi, kj, epos, aperm);
    aggregate_kernel<<<WBLK, 256>>>(h2, aperm, pack, off, ahi, alo);
    wsplit_t<<<dim3(HIDD / 32, (NR * HIDD) / 32), dim3(32, 32)>>>(c2w, wthi, wtlo, NR * HIDD, HIDD);
    gemm_mma<128><<<dim3(GMM, 2), 256, SMEM128>>>(ahi, alo, wthi, wtlo, c2b, nullptr,
                                                  hhi, hlo, NN, NR * HIDD, HIDD, 2);

    // head: h3 = relu(conv2_out @ w_out + b_out)  (N=64, K=256)
    wsplit_t<<<dim3(OUTD / 32, HIDD / 32), dim3(32, 32)>>>(w_out, wthi, wtlo, HIDD, OUTD);
    gemm_mma<64><<<dim3(GMM, 1), 256, SMEM64>>>(hhi, hlo, wthi, wtlo, b_out, h3,
                                                nullptr, nullptr, NN, HIDD, OUTD, 1);
    cls_kernel<<<WBLK, 256>>>(h3, w_cls, b_cls, out);
}

// round 5
// speedup vs baseline: 2.6905x; 2.6905x over previous
#include <cuda_runtime.h>
#include <cuda_fp16.h>
#include <cstdint>
#include <math.h>

#define NN   50000
#define NE   320000
#define NR   3
#define IND  768
#define HIDD 256
#define OUTD 64

// ---------------- scratch ----------------------------------------------------------
__device__ __align__(16) half  g_a16[(size_t)NN * IND];   // GEMM A (x, then s of convs)
__device__ __align__(16) half  g_w16[HIDD * IND];         // transposed weights [N,K] fp16
__device__ __align__(16) half  g_h16[NN * HIDD];          // conv2 output fp16 (head A)
__device__ float g_h0[NN * HIDD];
__device__ float g_h2[NN * HIDD];
__device__ float g_h3[NN * OUTD];
__device__ float g_qi[NN * NR];
__device__ float g_kj[NN * NR];
__device__ float g_aperm[NE];
__device__ int   g_cnt[NN];
__device__ int   g_off[NN + 1];
__device__ int   g_pack[NE];
__device__ int   g_epos[NE];
__device__ float g_wq[NR * HIDD];
__device__ float g_wk[NR * HIDD];

// ---------------- helpers ----------------------------------------------------------
__device__ __forceinline__ uint32_t smem_u32(const void* p) {
    uint32_t a;
    asm("{ .reg .u64 t; cvta.to.shared.u64 t, %1; cvt.u32.u64 %0, t; }" : "=r"(a) : "l"(p));
    return a;
}
#define SW128(o) ((o) ^ (((o) >> 3) & 0x70))

#define LDSM4(r0, r1, r2, r3, addr) \
    asm volatile("ldmatrix.sync.aligned.m8n8.x4.shared.b16 {%0,%1,%2,%3}, [%4];" \
        : "=r"(r0), "=r"(r1), "=r"(r2), "=r"(r3) : "r"(addr))

#define MMAF16(cf, af, b0, b1) \
    asm volatile("mma.sync.aligned.m16n8k16.row.col.f32.f16.f16.f32 " \
        "{%0,%1,%2,%3}, {%4,%5,%6,%7}, {%8,%9}, {%0,%1,%2,%3};" \
        : "+f"((cf)[0]), "+f"((cf)[1]), "+f"((cf)[2]), "+f"((cf)[3]) \
        : "r"((af)[0]), "r"((af)[1]), "r"((af)[2]), "r"((af)[3]), "r"(b0), "r"(b1))

#define CP_ASYNC16(dst, src) \
    asm volatile("cp.async.cg.shared.global [%0], [%1], 16;" :: "r"(dst), "l"(src))
#define CP_COMMIT() asm volatile("cp.async.commit_group;" ::: "memory")

// ---------------- fp16 single-pass GEMM, cp.async double-buffered -------------------
// C[M,N] = A[M,K] @ B^T (B stored [N,K] K-major), fp16 inputs, fp32 accumulate.
// CTA tile 128 x NBLK. mode: 0=f32 out, 1=f32+relu, 2=fp16 out.
template<int NBLK>
__global__ void __launch_bounds__(256, 2)
gemm_mma(const half* __restrict__ A, const half* __restrict__ B,
         const float* __restrict__ bias, float* __restrict__ C,
         half* __restrict__ C16, int M, int K, int N, int mode)
{
    constexpr int WN = NBLK / 32;
    constexpr int WM = 8 / WN;
    constexpr int MT = 128 / WM / 16;
    constexpr uint32_t STAGE = 16384u + (uint32_t)NBLK * 128u;

    extern __shared__ char smem[];
    const uint32_t sbase = smem_u32(smem);

    const int tid = threadIdx.x, wid = tid >> 5, lane = tid & 31;
    const int bm = blockIdx.x * 128;
    const int bn = blockIdx.y * NBLK;
    const int warp_m = wid / WN, warp_n = wid % WN;
    const int m0 = warp_m * (MT * 16);
    const int n0 = warp_n * 32;

    float c[MT][4][4];
#pragma unroll
    for (int i = 0; i < MT; i++)
#pragma unroll
        for (int j = 0; j < 4; j++)
#pragma unroll
            for (int l = 0; l < 4; l++) c[i][j][l] = 0.f;

    const int a_row = (lane & 15);
    const uint32_t a_sel = (uint32_t)((lane >> 4) << 4);
    const int b_row = (lane & 7) + ((lane >> 4) << 3);
    const uint32_t b_sel = (uint32_t)((lane & 8) << 1);

    const int NCH = K >> 6;

    // ---- async chunk loader ----
    auto load_chunk = [&](int ch, int st) {
        const uint32_t sA = sbase + (uint32_t)st * STAGE;
        const uint32_t sB = sA + 16384u;
        const size_t kofs = (size_t)ch * 64;
        for (int i = tid; i < 1024; i += 256) {
            int row = i >> 3, ck = i & 7;
            int gr = bm + row; if (gr > M - 1) gr = M - 1;
            uint32_t d = sA + SW128((uint32_t)(row * 128 + ck * 16));
            const char* g = (const char*)(A + (size_t)gr * K + kofs) + ck * 16;
            CP_ASYNC16(d, g);
        }
        for (int i = tid; i < NBLK * 8; i += 256) {
            int row = i >> 3, ck = i & 7;
            uint32_t d = sB + SW128((uint32_t)(row * 128 + ck * 16));
            const char* g = (const char*)(B + (size_t)(bn + row) * K + kofs) + ck * 16;
            CP_ASYNC16(d, g);
        }
        CP_COMMIT();
    };

    load_chunk(0, 0);

    for (int ch = 0; ch < NCH; ch++) {
        if (ch + 1 < NCH) {
            load_chunk(ch + 1, (ch + 1) & 1);
            asm volatile("cp.async.wait_group 1;" ::: "memory");
        } else {
            asm volatile("cp.async.wait_group 0;" ::: "memory");
        }
        __syncthreads();

        const uint32_t sA = sbase + (uint32_t)(ch & 1) * STAGE;
        const uint32_t sB = sA + 16384u;
#pragma unroll
        for (int ks = 0; ks < 4; ks++) {
            uint32_t b[4][2];
#pragma unroll
            for (int np = 0; np < 4; np += 2) {
                int row = n0 + np * 8 + b_row;
                uint32_t off = SW128((uint32_t)(row * 128 + ks * 32) + b_sel);
                LDSM4(b[np][0], b[np][1], b[np + 1][0], b[np + 1][1], sB + off);
            }
            uint32_t a[MT][4];
#pragma unroll
            for (int mt = 0; mt < MT; mt++) {
                int row = m0 + mt * 16 + a_row;
                uint32_t off = SW128((uint32_t)(row * 128 + ks * 32) + a_sel);
                LDSM4(a[mt][0], a[mt][1], a[mt][2], a[mt][3], sA + off);
            }
#pragma unroll
            for (int mt = 0; mt < MT; mt++)
#pragma unroll
                for (int nt = 0; nt < 4; nt++)
                    MMAF16(c[mt][nt], a[mt], b[nt][0], b[nt][1]);
        }
        __syncthreads();
    }

    // epilogue: rows lane/4 (+8), cols (lane%4)*2 (+1)
#pragma unroll
    for (int mt = 0; mt < MT; mt++) {
#pragma unroll
        for (int nt = 0; nt < 4; nt++) {
            int col = bn + n0 + nt * 8 + (lane & 3) * 2;
            float b0 = bias[col], b1 = bias[col + 1];
#pragma unroll
            for (int h = 0; h < 2; h++) {
                int r = bm + m0 + mt * 16 + (lane >> 2) + h * 8;
                if (r >= M) continue;
                float v0 = c[mt][nt][h * 2 + 0] + b0;
                float v1 = c[mt][nt][h * 2 + 1] + b1;
                if (mode == 1) { v0 = fmaxf(v0, 0.f); v1 = fmaxf(v1, 0.f); }
                if (mode == 2) {
                    ushort2 p = make_ushort2(__half_as_ushort(__float2half_rn(v0)),
                                             __half_as_ushort(__float2half_rn(v1)));
                    *(ushort2*)(C16 + (size_t)r * N + col) = p;
                } else {
                    *(float2*)(C + (size_t)r * N + col) = make_float2(v0, v1);
                }
            }
        }
    }
}

// ---------------- conversions ------------------------------------------------------
__global__ void tofp16(const float* __restrict__ src, half* __restrict__ dst, size_t n)
{
    size_t i = ((size_t)blockIdx.x * blockDim.x + threadIdx.x) * 8;
    if (i >= n) return;
    float4 a = *(const float4*)(src + i);
    float4 b = *(const float4*)(src + i + 4);
    float v[8] = {a.x, a.y, a.z, a.w, b.x, b.y, b.z, b.w};
    uint4 o;
    unsigned short* p = (unsigned short*)&o;
#pragma unroll
    for (int j = 0; j < 8; j++) p[j] = __half_as_ushort(__float2half_rn(v[j]));
    *(uint4*)(dst + i) = o;
}

// W[K,N] fp32 -> T[N,K] fp16 (transpose)
__global__ void wt16(const float* __restrict__ W, half* __restrict__ T, int K, int N)
{
    __shared__ float t[32][33];
    int n0 = blockIdx.x * 32, k0 = blockIdx.y * 32;
    t[threadIdx.y][threadIdx.x] = W[(size_t)(k0 + threadIdx.y) * N + n0 + threadIdx.x];
    __syncthreads();
    float v = t[threadIdx.x][threadIdx.y];
    T[(size_t)(n0 + threadIdx.y) * K + k0 + threadIdx.x] = __float2half_rn(v);
}

// ---------------- CSR construction -------------------------------------------------
__global__ void hist_kernel(const int* __restrict__ ei, int* __restrict__ cnt)
{
    int e = blockIdx.x * blockDim.x + threadIdx.x;
    if (e < NE) atomicAdd(&cnt[ei[NE + e]], 1);
}

__global__ void scan_kernel(const int* __restrict__ cnt, int* __restrict__ off)
{
    __shared__ int sums[1024];
    const int t = threadIdx.x;
    const int CH = (NN + 1023) / 1024;
    const int base = t * CH;
    int mysum = 0;
    for (int i = 0; i < CH; i++) {
        int idx = base + i;
        if (idx < NN) mysum += cnt[idx];
    }
    sums[t] = mysum;
    __syncthreads();
    for (int d = 1; d < 1024; d <<= 1) {
        int v = 0;
        if (t >= d) v = sums[t - d];
        __syncthreads();
        sums[t] += v;
        __syncthreads();
    }
    int run = sums[t] - mysum;
    for (int i = 0; i < CH; i++) {
        int idx = base + i;
        if (idx < NN) { off[idx] = run; run += cnt[idx]; }
    }
    if (t == 1023) off[NN] = sums[1023];
}

__global__ void fill_kernel(const int* __restrict__ ei, const int* __restrict__ etp,
                            const int* __restrict__ off, int* __restrict__ cur,
                            int* __restrict__ pack, int* __restrict__ epos)
{
    int e = blockIdx.x * blockDim.x + threadIdx.x;
    if (e >= NE) return;
    int d = ei[NE + e];
    int p = off[d] + atomicAdd(&cur[d], 1);
    pack[p] = ei[e] | (etp[e] << 20);
    epos[e] = p;
}

// ---------------- attention scalar path --------------------------------------------
__global__ void wqwk_kernel(const float* __restrict__ W, const float* __restrict__ q,
                            const float* __restrict__ k,
                            float* __restrict__ wq, float* __restrict__ wk)
{
    __shared__ float qs[HIDD], ks[HIDD];
    int r = blockIdx.x, c = threadIdx.x;
    qs[c] = q[c]; ks[c] = k[c];
    __syncthreads();
    const float* Wrc = W + ((size_t)r * HIDD + c) * HIDD;
    float aq = 0.f, ak = 0.f;
    for (int o = 0; o < HIDD; o++) {
        float w = Wrc[o];
        aq = fmaf(w, qs[o], aq);
        ak = fmaf(w, ks[o], ak);
    }
    wq[r * HIDD + c] = aq;
    wk[r * HIDD + c] = ak;
}

__global__ void qikj_kernel(const float* __restrict__ h, const float* __restrict__ wq,
                            const float* __restrict__ wk,
                            float* __restrict__ qi, float* __restrict__ kj)
{
    int warp = (blockIdx.x * blockDim.x + threadIdx.x) >> 5;
    int lane = threadIdx.x & 31;
    if (warp >= NN) return;
    const float4* hp = (const float4*)(h + (size_t)warp * HIDD + lane * 8);
    float4 h0 = hp[0], h1 = hp[1];
    float dq[NR], dk[NR];
#pragma unroll
    for (int r = 0; r < NR; r++) {
        const float4* qp = (const float4*)(wq + r * HIDD + lane * 8);
        const float4* kp = (const float4*)(wk + r * HIDD + lane * 8);
        float4 q0 = qp[0], q1 = qp[1];
        float4 k0 = kp[0], k1 = kp[1];
        dq[r] = h0.x*q0.x + h0.y*q0.y + h0.z*q0.z + h0.w*q0.w
              + h1.x*q1.x + h1.y*q1.y + h1.z*q1.z + h1.w*q1.w;
        dk[r] = h0.x*k0.x + h0.y*k0.y + h0.z*k0.z + h0.w*k0.w
              + h1.x*k1.x + h1.y*k1.y + h1.z*k1.z + h1.w*k1.w;
    }
#pragma unroll
    for (int d = 16; d; d >>= 1) {
#pragma unroll
        for (int r = 0; r < NR; r++) {
            dq[r] += __shfl_xor_sync(0xffffffffu, dq[r], d);
            dk[r] += __shfl_xor_sync(0xffffffffu, dk[r], d);
        }
    }
    if (lane == 0) {
#pragma unroll
        for (int r = 0; r < NR; r++) {
            qi[warp * NR + r] = dq[r];
            kj[warp * NR + r] = dk[r];
        }
    }
}

__global__ void alpha_kernel(const int* __restrict__ ei, const int* __restrict__ etp,
                             const float* __restrict__ qi, const float* __restrict__ kj,
                             const int* __restrict__ epos, float* __restrict__ aperm)
{
    int e = blockIdx.x * blockDim.x + threadIdx.x;
    if (e >= NE) return;
    int s = ei[e], d = ei[NE + e], t = etp[e];
    float a = qi[d * NR + t] + kj[s * NR + t];
    a = (a > 0.f) ? a : 0.2f * a;
    aperm[epos[e]] = a;
}

// ---------------- softmax + aggregation; emits fp16 directly ------------------------
__device__ __forceinline__ void store_half8(half* dst, const float* v)
{
    uint4 o;
    unsigned short* p = (unsigned short*)&o;
#pragma unroll
    for (int j = 0; j < 8; j++) p[j] = __half_as_ushort(__float2half_rn(v[j]));
    *(uint4*)dst = o;
}

__global__ void aggregate_kernel(const float* __restrict__ h, const float* __restrict__ aperm,
                                 const int* __restrict__ pack, const int* __restrict__ off,
                                 half* __restrict__ s16)
{
    int node = (blockIdx.x * blockDim.x + threadIdx.x) >> 5;
    int lane = threadIdx.x & 31;
    if (node >= NN) return;
    int o0 = off[node], o1 = off[node + 1];

    float a0[8], a1[8], a2[8];
#pragma unroll
    for (int j = 0; j < 8; j++) { a0[j] = 0.f; a1[j] = 0.f; a2[j] = 0.f; }

    if (o1 > o0) {
        float m = -3.4e38f;
        for (int p = o0 + lane; p < o1; p += 32) m = fmaxf(m, aperm[p]);
#pragma unroll
        for (int d = 16; d; d >>= 1) m = fmaxf(m, __shfl_xor_sync(0xffffffffu, m, d));
        float ssum = 0.f;
        for (int p = o0 + lane; p < o1; p += 32) ssum += __expf(aperm[p] - m);
#pragma unroll
        for (int d = 16; d; d >>= 1) ssum += __shfl_xor_sync(0xffffffffu, ssum, d);
        float inv = 1.f / (ssum + 1e-16f);

        for (int p = o0; p < o1; p++) {
            float w = __expf(aperm[p] - m) * inv;
            int pk = pack[p];
            int srcn = pk & 0xFFFFF;
            int t = pk >> 20;
            const float4* hp = (const float4*)(h + (size_t)srcn * HIDD + lane * 8);
            float4 v0 = hp[0], v1 = hp[1];
            float* a = (t == 0) ? a0 : (t == 1) ? a1 : a2;
            a[0] = fmaf(w, v0.x, a[0]); a[1] = fmaf(w, v0.y, a[1]);
            a[2] = fmaf(w, v0.z, a[2]); a[3] = fmaf(w, v0.w, a[3]);
            a[4] = fmaf(w, v1.x, a[4]); a[5] = fmaf(w, v1.y, a[5]);
            a[6] = fmaf(w, v1.z, a[6]); a[7] = fmaf(w, v1.w, a[7]);
        }
    }
    size_t base = (size_t)node * (NR * HIDD) + lane * 8;
    store_half8(s16 + base,       a0);
    store_half8(s16 + base + 256, a1);
    store_half8(s16 + base + 512, a2);
}

// ---------------- classifier -------------------------------------------------------
__global__ void cls_kernel(const float* __restrict__ h3, const float* __restrict__ w_cls,
                           const float* __restrict__ b_cls, float* __restrict__ out)
{
    int node = (blockIdx.x * blockDim.x + threadIdx.x) >> 5;
    int lane = threadIdx.x & 31;
    if (node >= NN) return;
    float2 v = *(const float2*)(h3 + (size_t)node * OUTD + lane * 2);
    float4 w = *(const float4*)(w_cls + lane * 4);
    float s0 = v.x * w.x + v.y * w.z;
    float s1 = v.x * w.y + v.y * w.w;
#pragma unroll
    for (int d = 16; d; d >>= 1) {
        s0 += __shfl_xor_sync(0xffffffffu, s0, d);
        s1 += __shfl_xor_sync(0xffffffffu, s1, d);
    }
    if (lane == 0) {
        out[node * 2 + 0] = s0 + b_cls[0];
        out[node * 2 + 1] = s1 + b_cls[1];
    }
}

// ---------------- launcher ---------------------------------------------------------
extern "C" void kernel_launch(void* const* d_in, const int* in_sizes, int n_in,
                              void* d_out, int out_size)
{
    const float* x     = (const float*)d_in[0];
    const int*   ei    = (const int*)d_in[1];
    const int*   etp   = (const int*)d_in[2];
    const float* w_in  = (const float*)d_in[3];
    const float* b_in  = (const float*)d_in[4];
    const float* c1w   = (const float*)d_in[5];
    const float* c1q   = (const float*)d_in[6];
    const float* c1k   = (const float*)d_in[7];
    const float* c1b   = (const float*)d_in[8];
    const float* c2w   = (const float*)d_in[9];
    const float* c2q   = (const float*)d_in[10];
    const float* c2k   = (const float*)d_in[11];
    const float* c2b   = (const float*)d_in[12];
    const float* w_out = (const float*)d_in[13];
    const float* b_out = (const float*)d_in[14];
    const float* w_cls = (const float*)d_in[15];
    const float* b_cls = (const float*)d_in[16];
    float* out = (float*)d_out;

    half *a16, *w16, *h16;
    float *h0, *h2, *h3, *qi, *kj, *aperm, *wq, *wk;
    int *cnt, *off, *pack, *epos;
    cudaGetSymbolAddress((void**)&a16, g_a16);
    cudaGetSymbolAddress((void**)&w16, g_w16);
    cudaGetSymbolAddress((void**)&h16, g_h16);
    cudaGetSymbolAddress((void**)&h0, g_h0);
    cudaGetSymbolAddress((void**)&h2, g_h2);
    cudaGetSymbolAddress((void**)&h3, g_h3);
    cudaGetSymbolAddress((void**)&qi, g_qi);
    cudaGetSymbolAddress((void**)&kj, g_kj);
    cudaGetSymbolAddress((void**)&aperm, g_aperm);
    cudaGetSymbolAddress((void**)&wq, g_wq);
    cudaGetSymbolAddress((void**)&wk, g_wk);
    cudaGetSymbolAddress((void**)&cnt, g_cnt);
    cudaGetSymbolAddress((void**)&off, g_off);
    cudaGetSymbolAddress((void**)&pack, g_pack);
    cudaGetSymbolAddress((void**)&epos, g_epos);

    const int SMEM128 = 2 * (16384 + 128 * 128);   // 65536
    const int SMEM64  = 2 * (16384 + 64 * 128);    // 49152
    cudaFuncSetAttribute(gemm_mma<128>, cudaFuncAttributeMaxDynamicSharedMemorySize, SMEM128);
    cudaFuncSetAttribute(gemm_mma<64>,  cudaFuncAttributeMaxDynamicSharedMemorySize, SMEM64);

    const int EBLK = (NE + 255) / 256;
    const int WBLK = (NN * 32 + 255) / 256;
    const int GMM = (NN + 127) / 128;

    // input layer: h0 = relu(x @ w_in + b_in)
    tofp16<<<(int)(((size_t)NN * IND / 8 + 255) / 256), 256>>>(x, a16, (size_t)NN * IND);
    wt16<<<dim3(HIDD / 32, IND / 32), dim3(32, 32)>>>(w_in, w16, IND, HIDD);
    gemm_mma<128><<<dim3(GMM, 2), 256, SMEM128>>>(a16, w16, b_in, h0, nullptr,
                                                  NN, IND, HIDD, 1);

    // CSR by dst
    cudaMemsetAsync(cnt, 0, NN * sizeof(int));
    hist_kernel<<<EBLK, 256>>>(ei, cnt);
    scan_kernel<<<1, 1024>>>(cnt, off);
    cudaMemsetAsync(cnt, 0, NN * sizeof(int));
    fill_kernel<<<EBLK, 256>>>(ei, etp, off, cnt, pack, epos);

    // conv1: h2 = RGAT(h0)
    wqwk_kernel<<<NR, HIDD>>>(c1w, c1q, c1k, wq, wk);
    qikj_kernel<<<WBLK, 256>>>(h0, wq, wk, qi, kj);
    alpha_kernel<<<EBLK, 256>>>(ei, etp, qi, kj, epos, aperm);
    aggregate_kernel<<<WBLK, 256>>>(h0, aperm, pack, off, a16);
    wt16<<<dim3(HIDD / 32, (NR * HIDD) / 32), dim3(32, 32)>>>(c1w, w16, NR * HIDD, HIDD);
    gemm_mma<128><<<dim3(GMM, 2), 256, SMEM128>>>(a16, w16, c1b, h2, nullptr,
                                                  NN, NR * HIDD, HIDD, 0);

    // conv2: h16 = RGAT(h2) in fp16
    wqwk_kernel<<<NR, HIDD>>>(c2w, c2q, c2k, wq, wk);
    qikj_kernel<<<WBLK, 256>>>(h2, wq, wk, qi, kj);
    alpha_kernel<<<EBLK, 256>>>(ei, etp, qi, kj, epos, aperm);
    aggregate_kernel<<<WBLK, 256>>>(h2, aperm, pack, off, a16);
    wt16<<<dim3(HIDD / 32, (NR * HIDD) / 32), dim3(32, 32)>>>(c2w, w16, NR * HIDD, HIDD);
    gemm_mma<128><<<dim3(GMM, 2), 256, SMEM128>>>(a16, w16, c2b, nullptr, h16,
                                                  NN, NR * HIDD, HIDD, 2);

    // head: h3 = relu(h16 @ w_out + b_out)  (K=256, N=64)
    wt16<<<dim3(OUTD / 32, HIDD / 32), dim3(32, 32)>>>(w_out, w16, HIDD, OUTD);
    gemm_mma<64><<<dim3(GMM, 1), 256, SMEM64>>>(h16, w16, b_out, h3, nullptr,
                                                NN, HIDD, OUTD, 1);
    cls_kernel<<<WBLK, 256>>>(h3, w_cls, b_cls, out);
}